// round 6
// baseline (speedup 1.0000x reference)
#include <cuda_runtime.h>
#include <math.h>

// Problem constants
#define Bc   8
#define Sc   2048
#define Dc   1024
#define Hc   16
#define DHc  64
#define Mtot (Bc * Sc)          // 16384
#define SCALE 0.125f            // 1/sqrt(64)

// ---------------------------------------------------------------------------
// Scratch (device globals: allocation-free, zero-init BSS)
// ---------------------------------------------------------------------------
__device__ float g_q [(size_t)Mtot * Dc];        // mixed_query_layer [B,S,D]
__device__ float g_k [(size_t)Mtot * Dc];        // mixed_key_layer   [B,S,D]
__device__ float g_qs[(size_t)Bc * Hc * Sc];     // q_score           [B,H,S]
__device__ float g_pk[(size_t)Bc * Hc * DHc];    // pooled_k flat     [b][D]

// ---------------------------------------------------------------------------
// SGEMM: C[M,N] = A[M,K] @ W[K,N] + bias   (K = N = 1024, M = 16384)
//  MODE 0: C = g_q (A = hs, W = Wq)
//  MODE 2: C = g_k (A = hs, W = Wk)
//  MODE 1: A = g_q, A-tile column-scaled by g_pk[b][k]; epilogue += g_q (residual);
//          C = Cout (d_out), W = Wt.
// Tile: 128x128x16, 256 threads, 8x8 per thread.
// ---------------------------------------------------------------------------
template <int MODE>
__global__ __launch_bounds__(256) void sgemm_kernel(
    const float* __restrict__ Ain,
    const float* __restrict__ W,
    const float* __restrict__ bias,
    float* __restrict__ Cout)
{
    const int K = Dc, N = Dc;
    __shared__ float As[16][128];
    __shared__ float Bs[16][128];

    const int tid = threadIdx.x;
    const int tx  = tid & 15;
    const int ty  = tid >> 4;
    const int m0  = blockIdx.y * 128;
    const int n0  = blockIdx.x * 128;

    const float* A = (MODE == 1) ? (const float*)g_q : Ain;

    const float* cs = nullptr;
    if (MODE == 1) cs = g_pk + (size_t)(m0 / Sc) * Dc;   // 128 | 2048: tile is single-batch

    float acc[8][8];
    #pragma unroll
    for (int i = 0; i < 8; i++)
        #pragma unroll
        for (int j = 0; j < 8; j++) acc[i][j] = 0.0f;

    for (int k0 = 0; k0 < K; k0 += 16) {
        // A tile (128 x 16), transposed into As[k][m]
        #pragma unroll
        for (int l = 0; l < 2; l++) {
            int f   = tid + l * 256;
            int ar  = f >> 2;
            int ac4 = (f & 3) * 4;
            float4 v = *(const float4*)(A + (size_t)(m0 + ar) * K + k0 + ac4);
            if (MODE == 1) {
                v.x *= cs[k0 + ac4];
                v.y *= cs[k0 + ac4 + 1];
                v.z *= cs[k0 + ac4 + 2];
                v.w *= cs[k0 + ac4 + 3];
            }
            As[ac4    ][ar] = v.x;
            As[ac4 + 1][ar] = v.y;
            As[ac4 + 2][ar] = v.z;
            As[ac4 + 3][ar] = v.w;
        }
        // B tile (16 x 128)
        #pragma unroll
        for (int l = 0; l < 2; l++) {
            int f   = tid + l * 256;
            int br  = f >> 5;
            int bc4 = (f & 31) * 4;
            *(float4*)&Bs[br][bc4] =
                *(const float4*)(W + (size_t)(k0 + br) * N + n0 + bc4);
        }
        __syncthreads();

        #pragma unroll
        for (int kk = 0; kk < 16; kk++) {
            float a[8], b[8];
            #pragma unroll
            for (int i = 0; i < 8; i++) a[i] = As[kk][ty * 8 + i];
            #pragma unroll
            for (int j = 0; j < 8; j++) b[j] = Bs[kk][tx * 8 + j];
            #pragma unroll
            for (int i = 0; i < 8; i++)
                #pragma unroll
                for (int j = 0; j < 8; j++)
                    acc[i][j] += a[i] * b[j];
        }
        __syncthreads();
    }

    float* C = (MODE == 0) ? (float*)g_q : (MODE == 2) ? (float*)g_k : Cout;

    #pragma unroll
    for (int i = 0; i < 8; i++) {
        int m = m0 + ty * 8 + i;
        #pragma unroll
        for (int j = 0; j < 8; j += 4) {
            int n = n0 + tx * 8 + j;
            float4 o;
            o.x = acc[i][j]     + bias[n];
            o.y = acc[i][j + 1] + bias[n + 1];
            o.z = acc[i][j + 2] + bias[n + 2];
            o.w = acc[i][j + 3] + bias[n + 3];
            if (MODE == 1) {
                float4 r = *(const float4*)(g_q + (size_t)m * N + n);
                o.x += r.x; o.y += r.y; o.z += r.z; o.w += r.w;
            }
            *(float4*)(C + (size_t)m * N + n) = o;
        }
    }
}

// ---------------------------------------------------------------------------
// q_score[b,h,s] = (q[b,s,:] @ Wqa[:,h] + bqa[h]) * SCALE + mask[b,0,s]
// One 128-thread block per (b,s) row.
// ---------------------------------------------------------------------------
__global__ __launch_bounds__(128) void qscore_kernel(
    const float* __restrict__ Wqa,
    const float* __restrict__ bqa,
    const float* __restrict__ mask)
{
    const int row = blockIdx.x;       // b*S + s
    const int tid = threadIdx.x;

    float acc[16];
    #pragma unroll
    for (int h = 0; h < 16; h++) acc[h] = 0.0f;

    for (int d = tid; d < Dc; d += 128) {
        float qv = g_q[(size_t)row * Dc + d];
        const float4* wr = (const float4*)(Wqa + (size_t)d * 16);
        float4 w0 = wr[0], w1 = wr[1], w2 = wr[2], w3 = wr[3];
        acc[0]  += qv * w0.x; acc[1]  += qv * w0.y; acc[2]  += qv * w0.z; acc[3]  += qv * w0.w;
        acc[4]  += qv * w1.x; acc[5]  += qv * w1.y; acc[6]  += qv * w1.z; acc[7]  += qv * w1.w;
        acc[8]  += qv * w2.x; acc[9]  += qv * w2.y; acc[10] += qv * w2.z; acc[11] += qv * w2.w;
        acc[12] += qv * w3.x; acc[13] += qv * w3.y; acc[14] += qv * w3.z; acc[15] += qv * w3.w;
    }

    #pragma unroll
    for (int off = 16; off > 0; off >>= 1)
        #pragma unroll
        for (int h = 0; h < 16; h++)
            acc[h] += __shfl_down_sync(0xffffffffu, acc[h], off);

    __shared__ float red[4][16];
    const int lane = tid & 31, w = tid >> 5;
    if (lane == 0)
        #pragma unroll
        for (int h = 0; h < 16; h++) red[w][h] = acc[h];
    __syncthreads();

    if (tid < 16) {
        float v = red[0][tid] + red[1][tid] + red[2][tid] + red[3][tid];
        int b = row / Sc, s = row % Sc;
        v = (v + bqa[tid]) * SCALE + mask[(size_t)b * Sc + s];
        g_qs[((size_t)b * Hc + tid) * Sc + s] = v;
    }
}

// ---------------------------------------------------------------------------
// Block-wide softmax over ws[0..Sc) in smem; leaves unnormalized exp in ws,
// returns 1/sum. 256 threads.
// ---------------------------------------------------------------------------
__device__ __forceinline__ float block_softmax(float* ws, float* red, int tid)
{
    float m = -INFINITY;
    for (int s = tid; s < Sc; s += 256) m = fmaxf(m, ws[s]);
    #pragma unroll
    for (int off = 16; off > 0; off >>= 1)
        m = fmaxf(m, __shfl_xor_sync(0xffffffffu, m, off));
    if ((tid & 31) == 0) red[tid >> 5] = m;
    __syncthreads();
    m = red[0];
    #pragma unroll
    for (int w = 1; w < 8; w++) m = fmaxf(m, red[w]);
    __syncthreads();

    float sum = 0.0f;
    for (int s = tid; s < Sc; s += 256) { float e = expf(ws[s] - m); ws[s] = e; sum += e; }
    #pragma unroll
    for (int off = 16; off > 0; off >>= 1) sum += __shfl_xor_sync(0xffffffffu, sum, off);
    if ((tid & 31) == 0) red[tid >> 5] = sum;
    __syncthreads();
    sum = 0.0f;
    #pragma unroll
    for (int w = 0; w < 8; w++) sum += red[w];
    __syncthreads();
    return 1.0f / sum;
}

// ---------------------------------------------------------------------------
// One block per (b,h), 256 threads:
//   softmax1(q_score) -> pooled_q -> qk_score -> softmax2 -> pooled_k
// ---------------------------------------------------------------------------
__global__ __launch_bounds__(256) void pool_kernel(const float* __restrict__ mask)
{
    const int bh  = blockIdx.x;
    const int b   = bh / Hc, h = bh % Hc;
    const int tid = threadIdx.x;

    __shared__ float ws[Sc];        // 8 KB
    __shared__ float red[256];
    __shared__ float pq[DHc];

    const float* qbase = g_q + (size_t)b * Sc * Dc + h * DHc;
    const float* kbase = g_k + (size_t)b * Sc * Dc + h * DHc;

    for (int s = tid; s < Sc; s += 256) ws[s] = g_qs[(size_t)bh * Sc + s];
    __syncthreads();
    float inv1 = block_softmax(ws, red, tid);

    // pooled_q[d] = sum_s w[s] * q[b,s,h*64+d]
    const int d = tid & 63, g = tid >> 6;
    float acc = 0.0f;
    for (int s = g; s < Sc; s += 4)
        acc += ws[s] * qbase[(size_t)s * Dc + d];
    red[tid] = acc;
    __syncthreads();
    if (tid < 64)
        pq[tid] = (red[tid] + red[tid + 64] + red[tid + 128] + red[tid + 192]) * inv1;
    __syncthreads();

    // qk_score[s] = SCALE * <k[b,s,h,:], pooled_q> + mask
    for (int s = tid; s < Sc; s += 256) {
        const float* kr = kbase + (size_t)s * Dc;
        float dot = 0.0f;
        #pragma unroll
        for (int dd = 0; dd < 64; dd += 4) {
            float4 kv = *(const float4*)(kr + dd);
            dot += kv.x * pq[dd] + kv.y * pq[dd + 1] + kv.z * pq[dd + 2] + kv.w * pq[dd + 3];
        }
        ws[s] = dot * SCALE + mask[(size_t)b * Sc + s];
    }
    __syncthreads();
    float inv2 = block_softmax(ws, red, tid);

    // pooled_k[d] = sum_s w2[s] * k[b,s,h*64+d]
    float acc2 = 0.0f;
    for (int s = g; s < Sc; s += 4)
        acc2 += ws[s] * kbase[(size_t)s * Dc + d];
    red[tid] = acc2;
    __syncthreads();
    if (tid < 64)
        g_pk[(size_t)bh * DHc + tid] =
            (red[tid] + red[tid + 64] + red[tid + 128] + red[tid + 192]) * inv2;
}

// ---------------------------------------------------------------------------
extern "C" void kernel_launch(void* const* d_in, const int* in_sizes, int n_in,
                              void* d_out, int out_size)
{
    const float* hs   = (const float*)d_in[0];
    const float* mask = (const float*)d_in[1];
    const float* Wq   = (const float*)d_in[2];
    const float* bq   = (const float*)d_in[3];
    const float* Wqa  = (const float*)d_in[4];
    const float* bqa  = (const float*)d_in[5];
    const float* Wk   = (const float*)d_in[6];
    const float* bk   = (const float*)d_in[7];
    const float* Wt   = (const float*)d_in[8];
    const float* bt   = (const float*)d_in[9];
    float* out = (float*)d_out;

    dim3 ggrid(Dc / 128, Mtot / 128);                       // 8 x 128 CTAs
    sgemm_kernel<0><<<ggrid, 256>>>(hs, Wq, bq, nullptr);   // g_q = hs@Wq + bq
    sgemm_kernel<2><<<ggrid, 256>>>(hs, Wk, bk, nullptr);   // g_k = hs@Wk + bk
    qscore_kernel<<<Mtot, 128>>>(Wqa, bqa, mask);           // g_qs
    pool_kernel<<<Bc * Hc, 256>>>(mask);                    // g_pk
    sgemm_kernel<1><<<ggrid, 256>>>(nullptr, Wt, bt, out);  // out = (pk⊙q)@Wt + bt + q
}

// round 9
// speedup vs baseline: 1.6504x; 1.6504x over previous
#include <cuda_runtime.h>
#include <math.h>

// Problem constants
#define Bc   8
#define Sc   2048
#define Dc   1024
#define Hc   16
#define DHc  64
#define Mtot (Bc * Sc)          // 16384
#define SCALE 0.125f            // 1/sqrt(64)

// ---------------------------------------------------------------------------
// Scratch (device globals: allocation-free)
// ---------------------------------------------------------------------------
__device__ float g_q [(size_t)Mtot * Dc];        // mixed_query_layer [B,S,D]
__device__ float g_k [(size_t)Mtot * Dc];        // mixed_key_layer   [B,S,D]
__device__ float g_qs[(size_t)Bc * Hc * Sc];     // q_score           [B,H,S]
__device__ float g_pk[(size_t)Bc * Hc * DHc];    // pooled_k flat     [b][D]

// ---------------------------------------------------------------------------
// TF32 helpers
// ---------------------------------------------------------------------------
__device__ __forceinline__ float tf32r(float x) {
    float r;
    asm("cvt.rna.tf32.f32 %0, %1;" : "=f"(r) : "f"(x));
    return r;
}

__device__ __forceinline__ void mma_tf32(float c[4], const float a[4], const float b[2]) {
    asm volatile(
        "mma.sync.aligned.m16n8k8.row.col.f32.tf32.tf32.f32 "
        "{%0,%1,%2,%3}, {%4,%5,%6,%7}, {%8,%9}, {%0,%1,%2,%3};"
        : "+f"(c[0]), "+f"(c[1]), "+f"(c[2]), "+f"(c[3])
        : "r"(__float_as_uint(a[0])), "r"(__float_as_uint(a[1])),
          "r"(__float_as_uint(a[2])), "r"(__float_as_uint(a[3])),
          "r"(__float_as_uint(b[0])), "r"(__float_as_uint(b[1])));
}

// ---------------------------------------------------------------------------
// TF32 tensor-core GEMM. C[M,N] = A[M,K] @ W[K,N] + bias. K = N(out) = 1024.
//   MODE 0: fused QK projection. A = hs. Grid N-span = 2048:
//           n-blocks [0,1024) use (Wq,bq) -> g_q, [1024,2048) use (Wk,bk) -> g_k.
//   MODE 1: A = g_q with per-k column scale g_pk[b][k]; epilogue adds residual
//           g_q; output Cout (= d_out), W = Wt, bias = bt.
// Block tile 128x128x16, 256 threads, 8 warps (4m x 2n), warp tile 32x64,
// double-buffered smem with padded strides (conflict-free fragment loads).
// ---------------------------------------------------------------------------
#define BM 128
#define BN 128
#define BK 16
#define KPA 20      // As row stride (16 + 4 pad) -> (20r + c) % 32 all distinct
#define NPB 136     // Bs row stride (128 + 8 pad) -> (8k + n) % 32 all distinct

template <int MODE>
__global__ __launch_bounds__(256) void mma_gemm(
    const float* __restrict__ Ain,
    const float* __restrict__ W0, const float* __restrict__ b0,
    const float* __restrict__ W1, const float* __restrict__ b1,
    float* __restrict__ Cout)
{
    __shared__ float As[2][BM * KPA];   // 20480 B
    __shared__ float Bs[2][BK * NPB];   // 17408 B

    const int tid  = threadIdx.x;
    const int lane = tid & 31;
    const int wid  = tid >> 5;
    const int wm   = wid & 3;           // 0..3  -> 32-row slab
    const int wn   = wid >> 2;          // 0..1  -> 64-col slab
    const int m0   = blockIdx.y * BM;
    const int n0b  = blockIdx.x * BN;

    // Select weight / bias / output for this n-block
    const float* A;
    const float* W;
    const float* bias;
    float*       C;
    int          n0;
    const float* cs = nullptr;
    if (MODE == 0) {
        A = Ain;
        if (n0b < Dc) { W = W0; bias = b0; C = g_q; n0 = n0b; }
        else          { W = W1; bias = b1; C = g_k; n0 = n0b - Dc; }
    } else {
        A = g_q; W = W0; bias = b0; C = Cout; n0 = n0b;
        cs = g_pk + (size_t)(m0 / Sc) * Dc;     // 128 | 2048: tile is single-batch
    }

    // ---- global load coordinates (two float4 each for A and B per thread)
    const int arow = tid >> 2;              // 0..63 ; second load at +64
    const int acol = (tid & 3) * 4;         // 0,4,8,12
    const int brow = tid >> 5;              // 0..7  ; second load at +8
    const int bcol = (tid & 31) * 4;        // 0..124

    const float* Ag0 = A + (size_t)(m0 + arow)      * Dc + acol;
    const float* Ag1 = A + (size_t)(m0 + arow + 64) * Dc + acol;
    const float* Bg0 = W + (size_t)brow       * Dc + n0 + bcol;
    const float* Bg1 = W + (size_t)(brow + 8) * Dc + n0 + bcol;

    // ---- fragment coordinates
    const int fr  = lane >> 2;              // 0..7
    const int fc  = lane & 3;               // 0..3
    const int aoff = (wm * 32 + fr) * KPA + fc;     // + mt*16*KPA + ks*8 (+4)
    const int boff = wn * 64 + fr;                  // + nt*8 ; row = ks*8 + fc (+4)

    float acc[2][8][4];
    #pragma unroll
    for (int mt = 0; mt < 2; mt++)
        #pragma unroll
        for (int nt = 0; nt < 8; nt++)
            #pragma unroll
            for (int i = 0; i < 4; i++) acc[mt][nt][i] = 0.0f;

    // ---- prologue: tile 0 -> regs -> tf32 -> smem buf 0
    float4 ra0 = *(const float4*)Ag0;
    float4 ra1 = *(const float4*)Ag1;
    float4 rb0 = *(const float4*)Bg0;
    float4 rb1 = *(const float4*)Bg1;
    if (MODE == 1) {
        float4 s = *(const float4*)(cs + acol);
        ra0.x *= s.x; ra0.y *= s.y; ra0.z *= s.z; ra0.w *= s.w;
        ra1.x *= s.x; ra1.y *= s.y; ra1.z *= s.z; ra1.w *= s.w;
    }
    *(float4*)&As[0][arow * KPA + acol] =
        make_float4(tf32r(ra0.x), tf32r(ra0.y), tf32r(ra0.z), tf32r(ra0.w));
    *(float4*)&As[0][(arow + 64) * KPA + acol] =
        make_float4(tf32r(ra1.x), tf32r(ra1.y), tf32r(ra1.z), tf32r(ra1.w));
    *(float4*)&Bs[0][brow * NPB + bcol] =
        make_float4(tf32r(rb0.x), tf32r(rb0.y), tf32r(rb0.z), tf32r(rb0.w));
    *(float4*)&Bs[0][(brow + 8) * NPB + bcol] =
        make_float4(tf32r(rb1.x), tf32r(rb1.y), tf32r(rb1.z), tf32r(rb1.w));
    __syncthreads();

    const int NIT = Dc / BK;    // 64
    int buf = 0;

    for (int it = 0; it < NIT; it++) {
        // prefetch next tile into registers
        float4 na0, na1, nb0, nb1;
        const bool more = (it + 1 < NIT);
        if (more) {
            const int k0n = (it + 1) * BK;
            na0 = *(const float4*)(Ag0 + k0n);
            na1 = *(const float4*)(Ag1 + k0n);
            nb0 = *(const float4*)(Bg0 + (size_t)k0n * Dc);
            nb1 = *(const float4*)(Bg1 + (size_t)k0n * Dc);
            if (MODE == 1) {
                float4 s = *(const float4*)(cs + k0n + acol);
                na0.x *= s.x; na0.y *= s.y; na0.z *= s.z; na0.w *= s.w;
                na1.x *= s.x; na1.y *= s.y; na1.z *= s.z; na1.w *= s.w;
            }
        }

        // compute on current buffer
        const float* Asb = As[buf];
        const float* Bsb = Bs[buf];
        #pragma unroll
        for (int ks = 0; ks < 2; ks++) {
            float a[2][4], b[8][2];
            #pragma unroll
            for (int mt = 0; mt < 2; mt++) {
                const int base = aoff + mt * 16 * KPA + ks * 8;
                a[mt][0] = Asb[base];
                a[mt][1] = Asb[base + 8 * KPA];
                a[mt][2] = Asb[base + 4];
                a[mt][3] = Asb[base + 8 * KPA + 4];
            }
            #pragma unroll
            for (int nt = 0; nt < 8; nt++) {
                const int base = (ks * 8 + fc) * NPB + boff + nt * 8;
                b[nt][0] = Bsb[base];
                b[nt][1] = Bsb[base + 4 * NPB];
            }
            #pragma unroll
            for (int mt = 0; mt < 2; mt++)
                #pragma unroll
                for (int nt = 0; nt < 8; nt++)
                    mma_tf32(acc[mt][nt], a[mt], b[nt]);
        }

        if (more) {
            buf ^= 1;
            *(float4*)&As[buf][arow * KPA + acol] =
                make_float4(tf32r(na0.x), tf32r(na0.y), tf32r(na0.z), tf32r(na0.w));
            *(float4*)&As[buf][(arow + 64) * KPA + acol] =
                make_float4(tf32r(na1.x), tf32r(na1.y), tf32r(na1.z), tf32r(na1.w));
            *(float4*)&Bs[buf][brow * NPB + bcol] =
                make_float4(tf32r(nb0.x), tf32r(nb0.y), tf32r(nb0.z), tf32r(nb0.w));
            *(float4*)&Bs[buf][(brow + 8) * NPB + bcol] =
                make_float4(tf32r(nb1.x), tf32r(nb1.y), tf32r(nb1.z), tf32r(nb1.w));
            __syncthreads();
        }
    }

    // ---- epilogue: bias (+ residual for MODE 1)
    #pragma unroll
    for (int mt = 0; mt < 2; mt++) {
        const int r = m0 + wm * 32 + mt * 16 + fr;
        #pragma unroll
        for (int nt = 0; nt < 8; nt++) {
            const int c = n0 + wn * 64 + nt * 8 + fc * 2;
            float bx = bias[c], by = bias[c + 1];
            float2 v0 = make_float2(acc[mt][nt][0] + bx, acc[mt][nt][1] + by);
            float2 v1 = make_float2(acc[mt][nt][2] + bx, acc[mt][nt][3] + by);
            if (MODE == 1) {
                float2 r0 = *(const float2*)(g_q + (size_t)r * Dc + c);
                float2 r1 = *(const float2*)(g_q + (size_t)(r + 8) * Dc + c);
                v0.x += r0.x; v0.y += r0.y;
                v1.x += r1.x; v1.y += r1.y;
            }
            *(float2*)(C + (size_t)r * Dc + c)       = v0;
            *(float2*)(C + (size_t)(r + 8) * Dc + c) = v1;
        }
    }
}

// ---------------------------------------------------------------------------
// q_score[b,h,s] = (q[b,s,:] @ Wqa[:,h] + bqa[h]) * SCALE + mask[b,0,s]
// One 128-thread block per (b,s) row.
// ---------------------------------------------------------------------------
__global__ __launch_bounds__(128) void qscore_kernel(
    const float* __restrict__ Wqa,
    const float* __restrict__ bqa,
    const float* __restrict__ mask)
{
    const int row = blockIdx.x;       // b*S + s
    const int tid = threadIdx.x;

    float acc[16];
    #pragma unroll
    for (int h = 0; h < 16; h++) acc[h] = 0.0f;

    for (int d = tid; d < Dc; d += 128) {
        float qv = g_q[(size_t)row * Dc + d];
        const float4* wr = (const float4*)(Wqa + (size_t)d * 16);
        float4 w0 = wr[0], w1 = wr[1], w2 = wr[2], w3 = wr[3];
        acc[0]  += qv * w0.x; acc[1]  += qv * w0.y; acc[2]  += qv * w0.z; acc[3]  += qv * w0.w;
        acc[4]  += qv * w1.x; acc[5]  += qv * w1.y; acc[6]  += qv * w1.z; acc[7]  += qv * w1.w;
        acc[8]  += qv * w2.x; acc[9]  += qv * w2.y; acc[10] += qv * w2.z; acc[11] += qv * w2.w;
        acc[12] += qv * w3.x; acc[13] += qv * w3.y; acc[14] += qv * w3.z; acc[15] += qv * w3.w;
    }

    #pragma unroll
    for (int off = 16; off > 0; off >>= 1)
        #pragma unroll
        for (int h = 0; h < 16; h++)
            acc[h] += __shfl_down_sync(0xffffffffu, acc[h], off);

    __shared__ float red[4][16];
    const int lane = tid & 31, w = tid >> 5;
    if (lane == 0)
        #pragma unroll
        for (int h = 0; h < 16; h++) red[w][h] = acc[h];
    __syncthreads();

    if (tid < 16) {
        float v = red[0][tid] + red[1][tid] + red[2][tid] + red[3][tid];
        int b = row / Sc, s = row % Sc;
        v = (v + bqa[tid]) * SCALE + mask[(size_t)b * Sc + s];
        g_qs[((size_t)b * Hc + tid) * Sc + s] = v;
    }
}

// ---------------------------------------------------------------------------
// Block-wide softmax over ws[0..Sc) in smem; leaves unnormalized exp in ws,
// returns 1/sum. 256 threads.
// ---------------------------------------------------------------------------
__device__ __forceinline__ float block_softmax(float* ws, float* red, int tid)
{
    float m = -INFINITY;
    for (int s = tid; s < Sc; s += 256) m = fmaxf(m, ws[s]);
    #pragma unroll
    for (int off = 16; off > 0; off >>= 1)
        m = fmaxf(m, __shfl_xor_sync(0xffffffffu, m, off));
    if ((tid & 31) == 0) red[tid >> 5] = m;
    __syncthreads();
    m = red[0];
    #pragma unroll
    for (int w = 1; w < 8; w++) m = fmaxf(m, red[w]);
    __syncthreads();

    float sum = 0.0f;
    for (int s = tid; s < Sc; s += 256) { float e = expf(ws[s] - m); ws[s] = e; sum += e; }
    #pragma unroll
    for (int off = 16; off > 0; off >>= 1) sum += __shfl_xor_sync(0xffffffffu, sum, off);
    if ((tid & 31) == 0) red[tid >> 5] = sum;
    __syncthreads();
    sum = 0.0f;
    #pragma unroll
    for (int w = 0; w < 8; w++) sum += red[w];
    __syncthreads();
    return 1.0f / sum;
}

// ---------------------------------------------------------------------------
// One block per (b,h), 256 threads:
//   softmax1(q_score) -> pooled_q -> qk_score -> softmax2 -> pooled_k
// ---------------------------------------------------------------------------
__global__ __launch_bounds__(256) void pool_kernel(const float* __restrict__ mask)
{
    const int bh  = blockIdx.x;
    const int b   = bh / Hc, h = bh % Hc;
    const int tid = threadIdx.x;

    __shared__ float ws[Sc];        // 8 KB
    __shared__ float red[256];
    __shared__ float pq[DHc];

    const float* qbase = g_q + (size_t)b * Sc * Dc + h * DHc;
    const float* kbase = g_k + (size_t)b * Sc * Dc + h * DHc;

    for (int s = tid; s < Sc; s += 256) ws[s] = g_qs[(size_t)bh * Sc + s];
    __syncthreads();
    float inv1 = block_softmax(ws, red, tid);

    // pooled_q[d] = sum_s w[s] * q[b,s,h*64+d]
    const int d = tid & 63, g = tid >> 6;
    float acc = 0.0f;
    for (int s = g; s < Sc; s += 4)
        acc += ws[s] * qbase[(size_t)s * Dc + d];
    red[tid] = acc;
    __syncthreads();
    if (tid < 64)
        pq[tid] = (red[tid] + red[tid + 64] + red[tid + 128] + red[tid + 192]) * inv1;
    __syncthreads();

    // qk_score[s] = SCALE * <k[b,s,h,:], pooled_q> + mask
    for (int s = tid; s < Sc; s += 256) {
        const float* kr = kbase + (size_t)s * Dc;
        float dot = 0.0f;
        #pragma unroll
        for (int dd = 0; dd < 64; dd += 4) {
            float4 kv = *(const float4*)(kr + dd);
            dot += kv.x * pq[dd] + kv.y * pq[dd + 1] + kv.z * pq[dd + 2] + kv.w * pq[dd + 3];
        }
        ws[s] = dot * SCALE + mask[(size_t)b * Sc + s];
    }
    __syncthreads();
    float inv2 = block_softmax(ws, red, tid);

    // pooled_k[d] = sum_s w2[s] * k[b,s,h*64+d]
    float acc2 = 0.0f;
    for (int s = g; s < Sc; s += 4)
        acc2 += ws[s] * kbase[(size_t)s * Dc + d];
    red[tid] = acc2;
    __syncthreads();
    if (tid < 64)
        g_pk[(size_t)bh * DHc + tid] =
            (red[tid] + red[tid + 64] + red[tid + 128] + red[tid + 192]) * inv2;
}

// ---------------------------------------------------------------------------
extern "C" void kernel_launch(void* const* d_in, const int* in_sizes, int n_in,
                              void* d_out, int out_size)
{
    const float* hs   = (const float*)d_in[0];
    const float* mask = (const float*)d_in[1];
    const float* Wq   = (const float*)d_in[2];
    const float* bq   = (const float*)d_in[3];
    const float* Wqa  = (const float*)d_in[4];
    const float* bqa  = (const float*)d_in[5];
    const float* Wk   = (const float*)d_in[6];
    const float* bk   = (const float*)d_in[7];
    const float* Wt   = (const float*)d_in[8];
    const float* bt   = (const float*)d_in[9];
    float* out = (float*)d_out;

    // Fused QK projection: N-span 2048 (left half -> g_q, right half -> g_k)
    dim3 gqk(2 * Dc / BN, Mtot / BM);                       // 16 x 128
    mma_gemm<0><<<gqk, 256>>>(hs, Wq, bq, Wk, bk, nullptr);

    qscore_kernel<<<Mtot, 128>>>(Wqa, bqa, mask);           // g_qs
    pool_kernel<<<Bc * Hc, 256>>>(mask);                    // g_pk

    // out = (pk ⊙ q) @ Wt + bt + q
    dim3 gt(Dc / BN, Mtot / BM);                            // 8 x 128
    mma_gemm<1><<<gt, 256>>>(nullptr, Wt, bt, nullptr, nullptr, out);
}

// round 14
// speedup vs baseline: 2.7423x; 1.6616x over previous
#include <cuda_runtime.h>
#include <math.h>
#include <stdint.h>

// Problem constants
#define Bc   8
#define Sc   2048
#define Dc   1024
#define Hc   16
#define DHc  64
#define Mtot (Bc * Sc)          // 16384
#define SCALE 0.125f            // 1/sqrt(64)

// ---------------------------------------------------------------------------
// Scratch (device globals: allocation-free)
// ---------------------------------------------------------------------------
__device__ float g_q  [(size_t)Mtot * Dc];       // mixed_query_layer (exact f32)
__device__ float g_k  [(size_t)Mtot * Dc];       // mixed_key_layer   (exact f32)
__device__ float g_qs [(size_t)Bc * Hc * Sc];    // q_score [B,H,S]
__device__ float g_pk [(size_t)Bc * Hc * DHc];   // pooled_k flat [b][D]
__device__ float g_hsr[(size_t)Mtot * Dc];       // tf32-rounded hidden_states
__device__ float g_qr [(size_t)Mtot * Dc];       // tf32-rounded (q * pooled_k)
__device__ float g_wqr[(size_t)Dc * Dc];         // tf32-rounded Wq
__device__ float g_wkr[(size_t)Dc * Dc];         // tf32-rounded Wk
__device__ float g_wtr[(size_t)Dc * Dc];         // tf32-rounded Wt

// ---------------------------------------------------------------------------
// TF32 / cp.async helpers
// ---------------------------------------------------------------------------
__device__ __forceinline__ float tf32r(float x) {
    float r;
    asm("cvt.rna.tf32.f32 %0, %1;" : "=f"(r) : "f"(x));
    return r;
}

__device__ __forceinline__ void mma_tf32(float c[4], const float a[4], const float b[2]) {
    asm volatile(
        "mma.sync.aligned.m16n8k8.row.col.f32.tf32.tf32.f32 "
        "{%0,%1,%2,%3}, {%4,%5,%6,%7}, {%8,%9}, {%0,%1,%2,%3};"
        : "+f"(c[0]), "+f"(c[1]), "+f"(c[2]), "+f"(c[3])
        : "r"(__float_as_uint(a[0])), "r"(__float_as_uint(a[1])),
          "r"(__float_as_uint(a[2])), "r"(__float_as_uint(a[3])),
          "r"(__float_as_uint(b[0])), "r"(__float_as_uint(b[1])));
}

__device__ __forceinline__ uint32_t sptr(const void* p) {
    return (uint32_t)__cvta_generic_to_shared(p);
}
__device__ __forceinline__ void cp16(uint32_t dst, const float* src) {
    asm volatile("cp.async.cg.shared.global [%0], [%1], 16;" :: "r"(dst), "l"(src));
}
#define CP_COMMIT()  asm volatile("cp.async.commit_group;" ::: "memory")
#define CP_WAIT2()   asm volatile("cp.async.wait_group 2;"  ::: "memory")

// ---------------------------------------------------------------------------
// Elementwise tf32 rounding: out[i] = rna(in[i]), float4-vectorized
// ---------------------------------------------------------------------------
__global__ __launch_bounds__(256) void round_kernel(
    const float4* __restrict__ in, float4* __restrict__ out, int n4)
{
    int i = blockIdx.x * 256 + threadIdx.x;
    if (i < n4) {
        float4 v = in[i];
        out[i] = make_float4(tf32r(v.x), tf32r(v.y), tf32r(v.z), tf32r(v.w));
    }
}

// g_qr[row][d] = rna( g_q[row][d] * g_pk[b(row)][d] ) ; one block per row
__global__ __launch_bounds__(256) void scaleround_kernel()
{
    const int row = blockIdx.x;
    const int b   = row / Sc;
    const int d   = threadIdx.x * 4;
    float4 v = *(const float4*)(g_q  + (size_t)row * Dc + d);
    float4 s = *(const float4*)(g_pk + (size_t)b   * Dc + d);
    *(float4*)(g_qr + (size_t)row * Dc + d) =
        make_float4(tf32r(v.x * s.x), tf32r(v.y * s.y),
                    tf32r(v.z * s.z), tf32r(v.w * s.w));
}

// ---------------------------------------------------------------------------
// TF32 tensor-core GEMM with 4-stage cp.async pipeline.
// C[M,N] = A[M,K] @ W[K,N] + bias, A/W pre-rounded to tf32. K = N = 1024.
//   MODE 0: fused QK projection: n-blocks [0,1024) -> (g_wqr,bq) -> g_q,
//           [1024,2048) -> (g_wkr,bk) -> g_k. A = g_hsr.
//   MODE 1: A = g_qr (pre-scaled+rounded), W = g_wtr; epilogue adds residual
//           g_q; output Cout (= d_out).
// Block tile 128x128x8, 256 threads, 8 warps (4m x 2n), warp tile 32x64.
// ---------------------------------------------------------------------------
#define BM 128
#define BN 128
#define BKk 8
#define KPA 12      // As row stride (8+4 pad):  (12*fr + fc) % 32 all distinct
#define NPB 136     // Bs row stride (128+8 pad): (8*k + n) % 32 all distinct
#define STAGES 4
#define NIT (Dc / BKk)   // 128

template <int MODE>
__global__ __launch_bounds__(256) void mma_gemm(
    const float* __restrict__ A,
    const float* __restrict__ W0, const float* __restrict__ b0,
    const float* __restrict__ W1, const float* __restrict__ b1,
    float* __restrict__ Cout)
{
    __shared__ float As[STAGES][BM * KPA];   // 4 x 6144 B
    __shared__ float Bs[STAGES][BKk * NPB];  // 4 x 4352 B

    const int tid  = threadIdx.x;
    const int lane = tid & 31;
    const int wid  = tid >> 5;
    const int wm   = wid & 3;
    const int wn   = wid >> 2;
    const int m0   = blockIdx.y * BM;
    const int n0b  = blockIdx.x * BN;

    const float* W;
    const float* bias;
    float*       C;
    int          n0;
    if (MODE == 0) {
        if (n0b < Dc) { W = W0; bias = b0; C = g_q; n0 = n0b; }
        else          { W = W1; bias = b1; C = g_k; n0 = n0b - Dc; }
    } else {
        W = W0; bias = b0; C = Cout; n0 = n0b;
    }

    // ---- cp.async coordinates: one 16B copy per thread per tile (A and B)
    const int arow = tid >> 1;              // 0..127
    const int ac4  = (tid & 1) * 4;         // 0 or 4
    const int brow = tid >> 5;              // 0..7
    const int bc4  = (tid & 31) * 4;        // 0..124
    const float* Ag = A + (size_t)(m0 + arow) * Dc + ac4;
    const float* Bg = W + (size_t)brow * Dc + n0 + bc4;

    uint32_t sA[STAGES], sB[STAGES];
    #pragma unroll
    for (int s = 0; s < STAGES; s++) {
        sA[s] = sptr(&As[s][arow * KPA + ac4]);
        sB[s] = sptr(&Bs[s][brow * NPB + bc4]);
    }

    // ---- prologue: issue stages 0..2
    #pragma unroll
    for (int s = 0; s < STAGES - 1; s++) {
        cp16(sA[s], Ag + s * BKk);
        cp16(sB[s], Bg + (size_t)s * BKk * Dc);
        CP_COMMIT();
    }

    // ---- fragment coordinates
    const int fr   = lane >> 2;             // 0..7
    const int fc   = lane & 3;              // 0..3
    const int aoff = (wm * 32 + fr) * KPA + fc;
    const int boff = wn * 64 + fr;

    float acc[2][8][4];
    #pragma unroll
    for (int mt = 0; mt < 2; mt++)
        #pragma unroll
        for (int nt = 0; nt < 8; nt++)
            #pragma unroll
            for (int i = 0; i < 4; i++) acc[mt][nt][i] = 0.0f;

    #pragma unroll 4
    for (int it = 0; it < NIT; it++) {
        CP_WAIT2();                 // buffer it%4 complete (issued 3 iters ago)
        __syncthreads();

        const int sb = it & (STAGES - 1);
        const float* Asb = As[sb];
        const float* Bsb = Bs[sb];

        float a[2][4], b[8][2];
        #pragma unroll
        for (int mt = 0; mt < 2; mt++) {
            const int base = aoff + mt * 16 * KPA;
            a[mt][0] = Asb[base];
            a[mt][1] = Asb[base + 8 * KPA];
            a[mt][2] = Asb[base + 4];
            a[mt][3] = Asb[base + 8 * KPA + 4];
        }
        #pragma unroll
        for (int nt = 0; nt < 8; nt++) {
            const int bcol = boff + nt * 8;
            b[nt][0] = Bsb[fc * NPB + bcol];
            b[nt][1] = Bsb[(fc + 4) * NPB + bcol];
        }
        #pragma unroll
        for (int mt = 0; mt < 2; mt++)
            #pragma unroll
            for (int nt = 0; nt < 8; nt++)
                mma_tf32(acc[mt][nt], a[mt], b[nt]);

        // issue stage it+3 (writes buffer (it-1)%4: all warps finished that
        // buffer before this iteration's barrier)
        const int nx = it + STAGES - 1;
        if (nx < NIT) {
            const int s = nx & (STAGES - 1);
            cp16(sA[s], Ag + nx * BKk);
            cp16(sB[s], Bg + (size_t)nx * BKk * Dc);
        }
        CP_COMMIT();                // always commit to keep group count aligned
    }

    // ---- epilogue: bias (+ residual for MODE 1)
    #pragma unroll
    for (int mt = 0; mt < 2; mt++) {
        const int r = m0 + wm * 32 + mt * 16 + fr;
        #pragma unroll
        for (int nt = 0; nt < 8; nt++) {
            const int c = n0 + wn * 64 + nt * 8 + fc * 2;
            float bx = bias[c], by = bias[c + 1];
            float2 v0 = make_float2(acc[mt][nt][0] + bx, acc[mt][nt][1] + by);
            float2 v1 = make_float2(acc[mt][nt][2] + bx, acc[mt][nt][3] + by);
            if (MODE == 1) {
                float2 r0 = *(const float2*)(g_q + (size_t)r * Dc + c);
                float2 r1 = *(const float2*)(g_q + (size_t)(r + 8) * Dc + c);
                v0.x += r0.x; v0.y += r0.y;
                v1.x += r1.x; v1.y += r1.y;
            }
            *(float2*)(C + (size_t)r * Dc + c)       = v0;
            *(float2*)(C + (size_t)(r + 8) * Dc + c) = v1;
        }
    }
}

// ---------------------------------------------------------------------------
// q_score[b,h,s] = (q[b,s,:] @ Wqa[:,h] + bqa[h]) * SCALE + mask[b,0,s]
// One 128-thread block per (b,s) row.
// ---------------------------------------------------------------------------
__global__ __launch_bounds__(128) void qscore_kernel(
    const float* __restrict__ Wqa,
    const float* __restrict__ bqa,
    const float* __restrict__ mask)
{
    const int row = blockIdx.x;       // b*S + s
    const int tid = threadIdx.x;

    float acc[16];
    #pragma unroll
    for (int h = 0; h < 16; h++) acc[h] = 0.0f;

    for (int d = tid; d < Dc; d += 128) {
        float qv = g_q[(size_t)row * Dc + d];
        const float4* wr = (const float4*)(Wqa + (size_t)d * 16);
        float4 w0 = wr[0], w1 = wr[1], w2 = wr[2], w3 = wr[3];
        acc[0]  += qv * w0.x; acc[1]  += qv * w0.y; acc[2]  += qv * w0.z; acc[3]  += qv * w0.w;
        acc[4]  += qv * w1.x; acc[5]  += qv * w1.y; acc[6]  += qv * w1.z; acc[7]  += qv * w1.w;
        acc[8]  += qv * w2.x; acc[9]  += qv * w2.y; acc[10] += qv * w2.z; acc[11] += qv * w2.w;
        acc[12] += qv * w3.x; acc[13] += qv * w3.y; acc[14] += qv * w3.z; acc[15] += qv * w3.w;
    }

    #pragma unroll
    for (int off = 16; off > 0; off >>= 1)
        #pragma unroll
        for (int h = 0; h < 16; h++)
            acc[h] += __shfl_down_sync(0xffffffffu, acc[h], off);

    __shared__ float red[4][16];
    const int lane = tid & 31, w = tid >> 5;
    if (lane == 0)
        #pragma unroll
        for (int h = 0; h < 16; h++) red[w][h] = acc[h];
    __syncthreads();

    if (tid < 16) {
        float v = red[0][tid] + red[1][tid] + red[2][tid] + red[3][tid];
        int b = row / Sc, s = row % Sc;
        v = (v + bqa[tid]) * SCALE + mask[(size_t)b * Sc + s];
        g_qs[((size_t)b * Hc + tid) * Sc + s] = v;
    }
}

// ---------------------------------------------------------------------------
// Block-wide softmax over ws[0..Sc) in smem; leaves unnormalized exp in ws,
// returns 1/sum. 256 threads.
// ---------------------------------------------------------------------------
__device__ __forceinline__ float block_softmax(float* ws, float* red, int tid)
{
    float m = -INFINITY;
    for (int s = tid; s < Sc; s += 256) m = fmaxf(m, ws[s]);
    #pragma unroll
    for (int off = 16; off > 0; off >>= 1)
        m = fmaxf(m, __shfl_xor_sync(0xffffffffu, m, off));
    if ((tid & 31) == 0) red[tid >> 5] = m;
    __syncthreads();
    m = red[0];
    #pragma unroll
    for (int w = 1; w < 8; w++) m = fmaxf(m, red[w]);
    __syncthreads();

    float sum = 0.0f;
    for (int s = tid; s < Sc; s += 256) { float e = expf(ws[s] - m); ws[s] = e; sum += e; }
    #pragma unroll
    for (int off = 16; off > 0; off >>= 1) sum += __shfl_xor_sync(0xffffffffu, sum, off);
    if ((tid & 31) == 0) red[tid >> 5] = sum;
    __syncthreads();
    sum = 0.0f;
    #pragma unroll
    for (int w = 0; w < 8; w++) sum += red[w];
    __syncthreads();
    return 1.0f / sum;
}

// ---------------------------------------------------------------------------
// One block per (b,h), 256 threads:
//   softmax1(q_score) -> pooled_q -> qk_score -> softmax2 -> pooled_k
// ---------------------------------------------------------------------------
__global__ __launch_bounds__(256) void pool_kernel(const float* __restrict__ mask)
{
    const int bh  = blockIdx.x;
    const int b   = bh / Hc, h = bh % Hc;
    const int tid = threadIdx.x;

    __shared__ float ws[Sc];        // 8 KB
    __shared__ float red[256];
    __shared__ float pq[DHc];

    const float* qbase = g_q + (size_t)b * Sc * Dc + h * DHc;
    const float* kbase = g_k + (size_t)b * Sc * Dc + h * DHc;

    for (int s = tid; s < Sc; s += 256) ws[s] = g_qs[(size_t)bh * Sc + s];
    __syncthreads();
    float inv1 = block_softmax(ws, red, tid);

    // pooled_q[d] = sum_s w[s] * q[b,s,h*64+d]
    const int d = tid & 63, g = tid >> 6;
    float acc = 0.0f;
    for (int s = g; s < Sc; s += 4)
        acc += ws[s] * qbase[(size_t)s * Dc + d];
    red[tid] = acc;
    __syncthreads();
    if (tid < 64)
        pq[tid] = (red[tid] + red[tid + 64] + red[tid + 128] + red[tid + 192]) * inv1;
    __syncthreads();

    // qk_score[s] = SCALE * <k[b,s,h,:], pooled_q> + mask
    for (int s = tid; s < Sc; s += 256) {
        const float* kr = kbase + (size_t)s * Dc;
        float dot = 0.0f;
        #pragma unroll
        for (int dd = 0; dd < 64; dd += 4) {
            float4 kv = *(const float4*)(kr + dd);
            dot += kv.x * pq[dd] + kv.y * pq[dd + 1] + kv.z * pq[dd + 2] + kv.w * pq[dd + 3];
        }
        ws[s] = dot * SCALE + mask[(size_t)b * Sc + s];
    }
    __syncthreads();
    float inv2 = block_softmax(ws, red, tid);

    // pooled_k[d] = sum_s w2[s] * k[b,s,h*64+d]
    float acc2 = 0.0f;
    for (int s = g; s < Sc; s += 4)
        acc2 += ws[s] * kbase[(size_t)s * Dc + d];
    red[tid] = acc2;
    __syncthreads();
    if (tid < 64)
        g_pk[(size_t)bh * DHc + tid] =
            (red[tid] + red[tid + 64] + red[tid + 128] + red[tid + 192]) * inv2;
}

// ---------------------------------------------------------------------------
extern "C" void kernel_launch(void* const* d_in, const int* in_sizes, int n_in,
                              void* d_out, int out_size)
{
    const float* hs   = (const float*)d_in[0];
    const float* mask = (const float*)d_in[1];
    const float* Wq   = (const float*)d_in[2];
    const float* bq   = (const float*)d_in[3];
    const float* Wqa  = (const float*)d_in[4];
    const float* bqa  = (const float*)d_in[5];
    const float* Wk   = (const float*)d_in[6];
    const float* bk   = (const float*)d_in[7];
    const float* Wt   = (const float*)d_in[8];
    const float* bt   = (const float*)d_in[9];
    float* out = (float*)d_out;

    float* hsr; cudaGetSymbolAddress((void**)&hsr, g_hsr);
    float* wqr; cudaGetSymbolAddress((void**)&wqr, g_wqr);
    float* wkr; cudaGetSymbolAddress((void**)&wkr, g_wkr);
    float* wtr; cudaGetSymbolAddress((void**)&wtr, g_wtr);
    float* qr;  cudaGetSymbolAddress((void**)&qr,  g_qr);

    // Pre-round operands to tf32 (rna)
    const int nhs4 = Mtot * Dc / 4;      // 4,194,304
    const int nw4  = Dc * Dc / 4;        // 262,144
    round_kernel<<<(nhs4 + 255) / 256, 256>>>((const float4*)hs, (float4*)hsr, nhs4);
    round_kernel<<<(nw4  + 255) / 256, 256>>>((const float4*)Wq, (float4*)wqr, nw4);
    round_kernel<<<(nw4  + 255) / 256, 256>>>((const float4*)Wk, (float4*)wkr, nw4);
    round_kernel<<<(nw4  + 255) / 256, 256>>>((const float4*)Wt, (float4*)wtr, nw4);

    // Fused QK projection: N-span 2048 (left half -> g_q, right half -> g_k)
    dim3 gqk(2 * Dc / BN, Mtot / BM);                       // 16 x 128
    mma_gemm<0><<<gqk, 256>>>(hsr, wqr, bq, wkr, bk, nullptr);

    qscore_kernel<<<Mtot, 128>>>(Wqa, bqa, mask);           // g_qs
    pool_kernel<<<Bc * Hc, 256>>>(mask);                    // g_pk

    // g_qr = rna(q * pooled_k) ; then out = g_qr @ Wt + bt + q
    scaleround_kernel<<<Mtot, 256>>>();
    dim3 gt(Dc / BN, Mtot / BM);                            // 8 x 128
    mma_gemm<1><<<gt, 256>>>(qr, wtr, bt, nullptr, nullptr, out);
}

// round 16
// speedup vs baseline: 2.9671x; 1.0820x over previous
#include <cuda_runtime.h>
#include <math.h>
#include <stdint.h>

// Problem constants
#define Bc   8
#define Sc   2048
#define Dc   1024
#define Hc   16
#define DHc  64
#define Mtot (Bc * Sc)          // 16384
#define SCALE 0.125f            // 1/sqrt(64)

// ---------------------------------------------------------------------------
// Scratch (device globals: allocation-free)
// ---------------------------------------------------------------------------
__device__ float g_q  [(size_t)Mtot * Dc];       // mixed_query_layer (exact f32)
__device__ float g_k  [(size_t)Mtot * Dc];       // mixed_key_layer   (exact f32)
__device__ float g_qs [(size_t)Bc * Hc * Sc];    // q_score [B,H,S]
__device__ float g_pk [(size_t)Bc * Hc * DHc];   // pooled_k flat [b][D]
__device__ float g_hsr[(size_t)Mtot * Dc];       // tf32-rounded hidden_states
__device__ float g_qr [(size_t)Mtot * Dc];       // tf32-rounded (q * pooled_k)
__device__ float g_wqr[(size_t)Dc * Dc];         // tf32-rounded Wq
__device__ float g_wkr[(size_t)Dc * Dc];         // tf32-rounded Wk
__device__ float g_wtr[(size_t)Dc * Dc];         // tf32-rounded Wt

// ---------------------------------------------------------------------------
// TF32 / cp.async helpers
// ---------------------------------------------------------------------------
__device__ __forceinline__ float tf32r(float x) {
    float r;
    asm("cvt.rna.tf32.f32 %0, %1;" : "=f"(r) : "f"(x));
    return r;
}

__device__ __forceinline__ void mma_tf32(float c[4], const float a[4], const float b[2]) {
    asm volatile(
        "mma.sync.aligned.m16n8k8.row.col.f32.tf32.tf32.f32 "
        "{%0,%1,%2,%3}, {%4,%5,%6,%7}, {%8,%9}, {%0,%1,%2,%3};"
        : "+f"(c[0]), "+f"(c[1]), "+f"(c[2]), "+f"(c[3])
        : "r"(__float_as_uint(a[0])), "r"(__float_as_uint(a[1])),
          "r"(__float_as_uint(a[2])), "r"(__float_as_uint(a[3])),
          "r"(__float_as_uint(b[0])), "r"(__float_as_uint(b[1])));
}

__device__ __forceinline__ uint32_t sptr(const void* p) {
    return (uint32_t)__cvta_generic_to_shared(p);
}
__device__ __forceinline__ void cp16(uint32_t dst, const float* src) {
    asm volatile("cp.async.cg.shared.global [%0], [%1], 16;" :: "r"(dst), "l"(src));
}
#define CP_COMMIT()  asm volatile("cp.async.commit_group;" ::: "memory")
#define CP_WAIT1()   asm volatile("cp.async.wait_group 1;"  ::: "memory")

// ---------------------------------------------------------------------------
// Elementwise tf32 rounding
// ---------------------------------------------------------------------------
__global__ __launch_bounds__(256) void round_kernel(
    const float4* __restrict__ in, float4* __restrict__ out, int n4)
{
    int i = blockIdx.x * 256 + threadIdx.x;
    if (i < n4) {
        float4 v = in[i];
        out[i] = make_float4(tf32r(v.x), tf32r(v.y), tf32r(v.z), tf32r(v.w));
    }
}

// All three weight matrices in one launch: 1024 blocks per weight
__global__ __launch_bounds__(256) void round3_kernel(
    const float4* __restrict__ w0, float4* __restrict__ o0,
    const float4* __restrict__ w1, float4* __restrict__ o1,
    const float4* __restrict__ w2, float4* __restrict__ o2)
{
    const int seg = blockIdx.x >> 10;
    const int idx = (blockIdx.x & 1023) * 256 + threadIdx.x;
    const float4* in  = (seg == 0) ? w0 : (seg == 1) ? w1 : w2;
    float4*       out = (seg == 0) ? o0 : (seg == 1) ? o1 : o2;
    float4 v = in[idx];
    out[idx] = make_float4(tf32r(v.x), tf32r(v.y), tf32r(v.z), tf32r(v.w));
}

// g_qr[row][d] = rna( g_q[row][d] * g_pk[b(row)][d] ) ; one block per row
__global__ __launch_bounds__(256) void scaleround_kernel()
{
    const int row = blockIdx.x;
    const int b   = row / Sc;
    const int d   = threadIdx.x * 4;
    float4 v = *(const float4*)(g_q  + (size_t)row * Dc + d);
    float4 s = *(const float4*)(g_pk + (size_t)b   * Dc + d);
    *(float4*)(g_qr + (size_t)row * Dc + d) =
        make_float4(tf32r(v.x * s.x), tf32r(v.y * s.y),
                    tf32r(v.z * s.z), tf32r(v.w * s.w));
}

// ---------------------------------------------------------------------------
// TF32 tensor-core GEMM, BK=32, 3-stage cp.async, dynamic smem.
// C[M,N] = A[M,K] @ W[K,N] + bias, A/W pre-rounded to tf32. K = N = 1024.
//   MODE 0: fused QK projection: n-blocks [0,1024) -> (g_wqr,bq) -> g_q,
//           [1024,2048) -> (g_wkr,bk) -> g_k. A = g_hsr.
//   MODE 1: A = g_qr (pre-scaled+rounded), W = g_wtr; epilogue adds residual
//           g_q; output Cout (= d_out).
// Block tile 128x128x32, 256 threads, 8 warps (4m x 2n), warp tile 32x64.
// One barrier + one wait_group per 32-K (4 ks-substeps, 64 HMMA).
// ---------------------------------------------------------------------------
#define BM 128
#define BN 128
#define BKk 32
#define KPA 36      // As row stride (32+4): banks (4*fr+fc)%32 all distinct
#define NPB 136     // Bs row stride (128+8): banks (8*k+n)%32 all distinct
#define STAGES 3
#define NITn (Dc / BKk)            // 32
#define ASTAGE (BM * KPA)          // 4608 floats
#define BSTAGE (BKk * NPB)         // 4352 floats
#define GEMM_SMEM (STAGES * (ASTAGE + BSTAGE) * 4)   // 107520 B

template <int MODE>
__global__ __launch_bounds__(256, 2) void mma_gemm(
    const float* __restrict__ A,
    const float* __restrict__ W0, const float* __restrict__ b0,
    const float* __restrict__ W1, const float* __restrict__ b1,
    float* __restrict__ Cout)
{
    extern __shared__ float sm[];
    float* AsAll = sm;                         // STAGES x ASTAGE
    float* BsAll = sm + STAGES * ASTAGE;       // STAGES x BSTAGE

    const int tid  = threadIdx.x;
    const int lane = tid & 31;
    const int wid  = tid >> 5;
    const int wm   = wid & 3;
    const int wn   = wid >> 2;
    const int m0   = blockIdx.y * BM;
    const int n0b  = blockIdx.x * BN;

    const float* W;
    const float* bias;
    float*       C;
    int          n0;
    if (MODE == 0) {
        if (n0b < Dc) { W = W0; bias = b0; C = g_q; n0 = n0b; }
        else          { W = W1; bias = b1; C = g_k; n0 = n0b - Dc; }
    } else {
        W = W0; bias = b0; C = Cout; n0 = n0b;
    }

    // ---- cp.async coordinates: 4 x 16B per thread for A and for B per tile
    // A tile 128 x 32 floats: chunk = tid + 256l -> row = chunk/8, col4 = (chunk%8)*4
    // B tile  32 x 128 floats: chunk -> row = chunk/32, col4 = (chunk%32)*4
    uint32_t aog[4], bog[4];   // element offsets into A / W
    uint32_t aos[4], bos[4];   // byte offsets into a stage's As / Bs
    #pragma unroll
    for (int l = 0; l < 4; l++) {
        const int ch = tid + l * 256;
        const int arow = ch >> 3, ac4 = (ch & 7) * 4;
        const int brow = ch >> 5, bc4 = (ch & 31) * 4;
        aog[l] = (uint32_t)(m0 + arow) * Dc + ac4;
        bog[l] = (uint32_t)brow * Dc + n0 + bc4;
        aos[l] = (uint32_t)(arow * KPA + ac4) * 4u;
        bos[l] = (uint32_t)(brow * NPB + bc4) * 4u;
    }
    const uint32_t sAbase = sptr(AsAll);
    const uint32_t sBbase = sptr(BsAll);

    // ---- prologue: stages 0,1
    #pragma unroll
    for (int s = 0; s < STAGES - 1; s++) {
        const int koff = s * BKk;
        #pragma unroll
        for (int l = 0; l < 4; l++) {
            cp16(sAbase + s * (ASTAGE * 4) + aos[l], A + aog[l] + koff);
            cp16(sBbase + s * (BSTAGE * 4) + bos[l], W + bog[l] + (size_t)koff * Dc);
        }
        CP_COMMIT();
    }

    // ---- fragment coordinates
    const int fr   = lane >> 2;
    const int fc   = lane & 3;
    const int aoff = (wm * 32 + fr) * KPA + fc;
    const int boff = wn * 64 + fr;

    float acc[2][8][4];
    #pragma unroll
    for (int mt = 0; mt < 2; mt++)
        #pragma unroll
        for (int nt = 0; nt < 8; nt++)
            #pragma unroll
            for (int i = 0; i < 4; i++) acc[mt][nt][i] = 0.0f;

    int sb = 0;                 // it % 3
    int ns = STAGES - 1;        // (it+2) % 3
    for (int it = 0; it < NITn; it++) {
        CP_WAIT1();             // stage it complete (2 groups in flight at top)
        __syncthreads();

        // issue stage it+2 (buffer (it-1)%3 — drained before this barrier)
        const int nx = it + STAGES - 1;
        if (nx < NITn) {
            const int koff = nx * BKk;
            #pragma unroll
            for (int l = 0; l < 4; l++) {
                cp16(sAbase + ns * (ASTAGE * 4) + aos[l], A + aog[l] + koff);
                cp16(sBbase + ns * (BSTAGE * 4) + bos[l], W + bog[l] + (size_t)koff * Dc);
            }
        }
        CP_COMMIT();            // always commit to keep group count aligned

        const float* Asb = AsAll + sb * ASTAGE;
        const float* Bsb = BsAll + sb * BSTAGE;

        #pragma unroll
        for (int ks = 0; ks < 4; ks++) {
            float a[2][4], b[8][2];
            #pragma unroll
            for (int mt = 0; mt < 2; mt++) {
                const int base = aoff + mt * 16 * KPA + ks * 8;
                a[mt][0] = Asb[base];
                a[mt][1] = Asb[base + 8 * KPA];
                a[mt][2] = Asb[base + 4];
                a[mt][3] = Asb[base + 8 * KPA + 4];
            }
            const int kr = ks * 8 + fc;
            #pragma unroll
            for (int nt = 0; nt < 8; nt++) {
                const int bcol = boff + nt * 8;
                b[nt][0] = Bsb[kr * NPB + bcol];
                b[nt][1] = Bsb[(kr + 4) * NPB + bcol];
            }
            #pragma unroll
            for (int mt = 0; mt < 2; mt++)
                #pragma unroll
                for (int nt = 0; nt < 8; nt++)
                    mma_tf32(acc[mt][nt], a[mt], b[nt]);
        }

        sb = (sb == STAGES - 1) ? 0 : sb + 1;
        ns = (ns == STAGES - 1) ? 0 : ns + 1;
    }

    // ---- epilogue: bias (+ residual for MODE 1)
    #pragma unroll
    for (int mt = 0; mt < 2; mt++) {
        const int r = m0 + wm * 32 + mt * 16 + fr;
        #pragma unroll
        for (int nt = 0; nt < 8; nt++) {
            const int c = n0 + wn * 64 + nt * 8 + fc * 2;
            float bx = bias[c], by = bias[c + 1];
            float2 v0 = make_float2(acc[mt][nt][0] + bx, acc[mt][nt][1] + by);
            float2 v1 = make_float2(acc[mt][nt][2] + bx, acc[mt][nt][3] + by);
            if (MODE == 1) {
                float2 r0 = *(const float2*)(g_q + (size_t)r * Dc + c);
                float2 r1 = *(const float2*)(g_q + (size_t)(r + 8) * Dc + c);
                v0.x += r0.x; v0.y += r0.y;
                v1.x += r1.x; v1.y += r1.y;
            }
            *(float2*)(C + (size_t)r * Dc + c)       = v0;
            *(float2*)(C + (size_t)(r + 8) * Dc + c) = v1;
        }
    }
}

// ---------------------------------------------------------------------------
// q_score[b,h,s] = (q[b,s,:] @ Wqa[:,h] + bqa[h]) * SCALE + mask[b,0,s]
// One 128-thread block per (b,s) row.
// ---------------------------------------------------------------------------
__global__ __launch_bounds__(128) void qscore_kernel(
    const float* __restrict__ Wqa,
    const float* __restrict__ bqa,
    const float* __restrict__ mask)
{
    const int row = blockIdx.x;       // b*S + s
    const int tid = threadIdx.x;

    float acc[16];
    #pragma unroll
    for (int h = 0; h < 16; h++) acc[h] = 0.0f;

    for (int d = tid; d < Dc; d += 128) {
        float qv = g_q[(size_t)row * Dc + d];
        const float4* wr = (const float4*)(Wqa + (size_t)d * 16);
        float4 w0 = wr[0], w1 = wr[1], w2 = wr[2], w3 = wr[3];
        acc[0]  += qv * w0.x; acc[1]  += qv * w0.y; acc[2]  += qv * w0.z; acc[3]  += qv * w0.w;
        acc[4]  += qv * w1.x; acc[5]  += qv * w1.y; acc[6]  += qv * w1.z; acc[7]  += qv * w1.w;
        acc[8]  += qv * w2.x; acc[9]  += qv * w2.y; acc[10] += qv * w2.z; acc[11] += qv * w2.w;
        acc[12] += qv * w3.x; acc[13] += qv * w3.y; acc[14] += qv * w3.z; acc[15] += qv * w3.w;
    }

    #pragma unroll
    for (int off = 16; off > 0; off >>= 1)
        #pragma unroll
        for (int h = 0; h < 16; h++)
            acc[h] += __shfl_down_sync(0xffffffffu, acc[h], off);

    __shared__ float red[4][16];
    const int lane = tid & 31, w = tid >> 5;
    if (lane == 0)
        #pragma unroll
        for (int h = 0; h < 16; h++) red[w][h] = acc[h];
    __syncthreads();

    if (tid < 16) {
        float v = red[0][tid] + red[1][tid] + red[2][tid] + red[3][tid];
        int b = row / Sc, s = row % Sc;
        v = (v + bqa[tid]) * SCALE + mask[(size_t)b * Sc + s];
        g_qs[((size_t)b * Hc + tid) * Sc + s] = v;
    }
}

// ---------------------------------------------------------------------------
// Block-wide softmax over ws[0..Sc) in smem; leaves unnormalized exp in ws,
// returns 1/sum. 256 threads.
// ---------------------------------------------------------------------------
__device__ __forceinline__ float block_softmax(float* ws, float* red, int tid)
{
    float m = -INFINITY;
    for (int s = tid; s < Sc; s += 256) m = fmaxf(m, ws[s]);
    #pragma unroll
    for (int off = 16; off > 0; off >>= 1)
        m = fmaxf(m, __shfl_xor_sync(0xffffffffu, m, off));
    if ((tid & 31) == 0) red[tid >> 5] = m;
    __syncthreads();
    m = red[0];
    #pragma unroll
    for (int w = 1; w < 8; w++) m = fmaxf(m, red[w]);
    __syncthreads();

    float sum = 0.0f;
    for (int s = tid; s < Sc; s += 256) { float e = expf(ws[s] - m); ws[s] = e; sum += e; }
    #pragma unroll
    for (int off = 16; off > 0; off >>= 1) sum += __shfl_xor_sync(0xffffffffu, sum, off);
    if ((tid & 31) == 0) red[tid >> 5] = sum;
    __syncthreads();
    sum = 0.0f;
    #pragma unroll
    for (int w = 0; w < 8; w++) sum += red[w];
    __syncthreads();
    return 1.0f / sum;
}

// ---------------------------------------------------------------------------
// One block per (b,h), 256 threads:
//   softmax1(q_score) -> pooled_q -> qk_score -> softmax2 -> pooled_k
// ---------------------------------------------------------------------------
__global__ __launch_bounds__(256) void pool_kernel(const float* __restrict__ mask)
{
    const int bh  = blockIdx.x;
    const int b   = bh / Hc, h = bh % Hc;
    const int tid = threadIdx.x;

    __shared__ float ws[Sc];        // 8 KB
    __shared__ float red[256];
    __shared__ float pq[DHc];

    const float* qbase = g_q + (size_t)b * Sc * Dc + h * DHc;
    const float* kbase = g_k + (size_t)b * Sc * Dc + h * DHc;

    for (int s = tid; s < Sc; s += 256) ws[s] = g_qs[(size_t)bh * Sc + s];
    __syncthreads();
    float inv1 = block_softmax(ws, red, tid);

    // pooled_q[d] = sum_s w[s] * q[b,s,h*64+d]
    const int d = tid & 63, g = tid >> 6;
    float acc = 0.0f;
    for (int s = g; s < Sc; s += 4)
        acc += ws[s] * qbase[(size_t)s * Dc + d];
    red[tid] = acc;
    __syncthreads();
    if (tid < 64)
        pq[tid] = (red[tid] + red[tid + 64] + red[tid + 128] + red[tid + 192]) * inv1;
    __syncthreads();

    // qk_score[s] = SCALE * <k[b,s,h,:], pooled_q> + mask
    for (int s = tid; s < Sc; s += 256) {
        const float* kr = kbase + (size_t)s * Dc;
        float dot = 0.0f;
        #pragma unroll
        for (int dd = 0; dd < 64; dd += 4) {
            float4 kv = *(const float4*)(kr + dd);
            dot += kv.x * pq[dd] + kv.y * pq[dd + 1] + kv.z * pq[dd + 2] + kv.w * pq[dd + 3];
        }
        ws[s] = dot * SCALE + mask[(size_t)b * Sc + s];
    }
    __syncthreads();
    float inv2 = block_softmax(ws, red, tid);

    // pooled_k[d] = sum_s w2[s] * k[b,s,h*64+d]
    float acc2 = 0.0f;
    for (int s = g; s < Sc; s += 4)
        acc2 += ws[s] * kbase[(size_t)s * Dc + d];
    red[tid] = acc2;
    __syncthreads();
    if (tid < 64)
        g_pk[(size_t)bh * DHc + tid] =
            (red[tid] + red[tid + 64] + red[tid + 128] + red[tid + 192]) * inv2;
}

// ---------------------------------------------------------------------------
extern "C" void kernel_launch(void* const* d_in, const int* in_sizes, int n_in,
                              void* d_out, int out_size)
{
    const float* hs   = (const float*)d_in[0];
    const float* mask = (const float*)d_in[1];
    const float* Wq   = (const float*)d_in[2];
    const float* bq   = (const float*)d_in[3];
    const float* Wqa  = (const float*)d_in[4];
    const float* bqa  = (const float*)d_in[5];
    const float* Wk   = (const float*)d_in[6];
    const float* bk   = (const float*)d_in[7];
    const float* Wt   = (const float*)d_in[8];
    const float* bt   = (const float*)d_in[9];
    float* out = (float*)d_out;

    float* hsr; cudaGetSymbolAddress((void**)&hsr, g_hsr);
    float* wqr; cudaGetSymbolAddress((void**)&wqr, g_wqr);
    float* wkr; cudaGetSymbolAddress((void**)&wkr, g_wkr);
    float* wtr; cudaGetSymbolAddress((void**)&wtr, g_wtr);
    float* qr;  cudaGetSymbolAddress((void**)&qr,  g_qr);

    // Allow 105 KB dynamic smem on the GEMM kernels (idempotent host call)
    cudaFuncSetAttribute(mma_gemm<0>, cudaFuncAttributeMaxDynamicSharedMemorySize, GEMM_SMEM);
    cudaFuncSetAttribute(mma_gemm<1>, cudaFuncAttributeMaxDynamicSharedMemorySize, GEMM_SMEM);

    // Pre-round operands to tf32 (rna)
    const int nhs4 = Mtot * Dc / 4;      // 4,194,304
    round_kernel<<<(nhs4 + 255) / 256, 256>>>((const float4*)hs, (float4*)hsr, nhs4);
    round3_kernel<<<3072, 256>>>((const float4*)Wq, (float4*)wqr,
                                 (const float4*)Wk, (float4*)wkr,
                                 (const float4*)Wt, (float4*)wtr);

    // Fused QK projection: N-span 2048 (left half -> g_q, right half -> g_k)
    dim3 gqk(2 * Dc / BN, Mtot / BM);                       // 16 x 128
    mma_gemm<0><<<gqk, 256, GEMM_SMEM>>>(hsr, wqr, bq, wkr, bk, nullptr);

    qscore_kernel<<<Mtot, 128>>>(Wqa, bqa, mask);           // g_qs
    pool_kernel<<<Bc * Hc, 256>>>(mask);                    // g_pk

    // g_qr = rna(q * pooled_k) ; then out = g_qr @ Wt + bt + q
    scaleround_kernel<<<Mtot, 256>>>();
    dim3 gt(Dc / BN, Mtot / BM);                            // 8 x 128
    mma_gemm<1><<<gt, 256, GEMM_SMEM>>>(qr, wtr, bt, nullptr, nullptr, out);
}